// round 1
// baseline (speedup 1.0000x reference)
#include <cuda_runtime.h>
#include <math.h>

// ============================================================================
// CausalSelfAttention (no actual mask in reference) — fp32 baseline pipeline:
//   1) qkv_gemm:  Q,K,V = x @ W{q,k,v}^T     (NT sgemm, M=8192,N=1024,K=1024, z=3)
//   2) qk_gemm:   S_b = (Q_b @ K_b^T) / 32   (NT sgemm per batch, 2048x2048x1024)
//   3) softmax:   row softmax over S         (8192 rows x 2048)
//   4) pv_gemm:   O_b = S_b @ V_b            (NN sgemm per batch, 2048x1024x2048)
// Scratch in __device__ globals (allowed; no runtime allocation).
// ============================================================================

#define BM 128
#define BN 128
#define BK 16
#define TM 8
#define TN 8
#define NTHREADS 256

// Scratch: Q,K,V are [4*2048, 1024]; S is [4, 2048, 2048]
__device__ float g_Q[8192 * 1024];
__device__ float g_K[8192 * 1024];
__device__ float g_V[8192 * 1024];
__device__ float g_S[4 * 2048 * 2048];

// ----------------------------------------------------------------------------
// NT gemm tile body: C[M,N] = alpha * A[M,K] * B[N,K]^T (both row-major,
// K contiguous for both operands). All dims divisible by tile sizes.
// ----------------------------------------------------------------------------
__device__ __forceinline__ void gemm_nt_tile(
    const float* __restrict__ A, const float* __restrict__ B, float* __restrict__ C,
    int M, int N, int K, float alpha)
{
    __shared__ float As[BK][BM + 4];
    __shared__ float Bs[BK][BN + 4];

    const int tid = threadIdx.x;
    const int tx = tid & 15;   // 0..15 -> column group
    const int ty = tid >> 4;   // 0..15 -> row group
    const int row0 = blockIdx.y * BM;
    const int col0 = blockIdx.x * BN;

    // global-load mapping: 128 rows x 16 cols per tile, 2 float4 per thread
    const int lr = tid >> 2;          // 0..63
    const int lc = (tid & 3) << 2;    // 0,4,8,12
    const float* Ap = A + (size_t)(row0 + lr) * K + lc;
    const float* Bp = B + (size_t)(col0 + lr) * K + lc;

    float acc[TM][TN] = {};

    for (int k0 = 0; k0 < K; k0 += BK) {
        float4 a0 = *(const float4*)(Ap + k0);
        float4 a1 = *(const float4*)(Ap + (size_t)64 * K + k0);
        float4 b0 = *(const float4*)(Bp + k0);
        float4 b1 = *(const float4*)(Bp + (size_t)64 * K + k0);

        __syncthreads();   // previous iteration's compute done
        As[lc + 0][lr] = a0.x; As[lc + 1][lr] = a0.y;
        As[lc + 2][lr] = a0.z; As[lc + 3][lr] = a0.w;
        As[lc + 0][lr + 64] = a1.x; As[lc + 1][lr + 64] = a1.y;
        As[lc + 2][lr + 64] = a1.z; As[lc + 3][lr + 64] = a1.w;
        Bs[lc + 0][lr] = b0.x; Bs[lc + 1][lr] = b0.y;
        Bs[lc + 2][lr] = b0.z; Bs[lc + 3][lr] = b0.w;
        Bs[lc + 0][lr + 64] = b1.x; Bs[lc + 1][lr + 64] = b1.y;
        Bs[lc + 2][lr + 64] = b1.z; Bs[lc + 3][lr + 64] = b1.w;
        __syncthreads();

        #pragma unroll
        for (int kk = 0; kk < BK; ++kk) {
            float4 al = *(const float4*)&As[kk][ty * TM];
            float4 ah = *(const float4*)&As[kk][ty * TM + 4];
            float4 bl = *(const float4*)&Bs[kk][tx * TN];
            float4 bh = *(const float4*)&Bs[kk][tx * TN + 4];
            float af[TM] = {al.x, al.y, al.z, al.w, ah.x, ah.y, ah.z, ah.w};
            float bf[TN] = {bl.x, bl.y, bl.z, bl.w, bh.x, bh.y, bh.z, bh.w};
            #pragma unroll
            for (int i = 0; i < TM; ++i)
                #pragma unroll
                for (int j = 0; j < TN; ++j)
                    acc[i][j] += af[i] * bf[j];
        }
    }

    #pragma unroll
    for (int i = 0; i < TM; ++i) {
        #pragma unroll
        for (int j = 0; j < TN; j += 4) {
            float4 r;
            r.x = acc[i][j + 0] * alpha;
            r.y = acc[i][j + 1] * alpha;
            r.z = acc[i][j + 2] * alpha;
            r.w = acc[i][j + 3] * alpha;
            *(float4*)&C[(size_t)(row0 + ty * TM + i) * N + col0 + tx * TN + j] = r;
        }
    }
}

// ----------------------------------------------------------------------------
// NN gemm tile body: C[M,N] = A[M,K] * B[K,N] (row-major).
// ----------------------------------------------------------------------------
__device__ __forceinline__ void gemm_nn_tile(
    const float* __restrict__ A, const float* __restrict__ B, float* __restrict__ C,
    int M, int N, int K)
{
    __shared__ float As[BK][BM + 4];
    __shared__ float Bs[BK][BN + 4];

    const int tid = threadIdx.x;
    const int tx = tid & 15;
    const int ty = tid >> 4;
    const int row0 = blockIdx.y * BM;
    const int col0 = blockIdx.x * BN;

    const int lr = tid >> 2;          // A tile: 0..63
    const int lc = (tid & 3) << 2;
    const float* Ap = A + (size_t)(row0 + lr) * K + lc;

    const int brow = tid >> 5;        // B tile: 0..7
    const int bcol = (tid & 31) << 2; // 0..124
    const float* Bp = B + (size_t)brow * N + col0 + bcol;

    float acc[TM][TN] = {};

    for (int k0 = 0; k0 < K; k0 += BK) {
        float4 a0 = *(const float4*)(Ap + k0);
        float4 a1 = *(const float4*)(Ap + (size_t)64 * K + k0);
        float4 b0 = *(const float4*)(Bp + (size_t)k0 * N);
        float4 b1 = *(const float4*)(Bp + (size_t)(k0 + 8) * N);

        __syncthreads();
        As[lc + 0][lr] = a0.x; As[lc + 1][lr] = a0.y;
        As[lc + 2][lr] = a0.z; As[lc + 3][lr] = a0.w;
        As[lc + 0][lr + 64] = a1.x; As[lc + 1][lr + 64] = a1.y;
        As[lc + 2][lr + 64] = a1.z; As[lc + 3][lr + 64] = a1.w;
        *(float4*)&Bs[brow][bcol] = b0;
        *(float4*)&Bs[brow + 8][bcol] = b1;
        __syncthreads();

        #pragma unroll
        for (int kk = 0; kk < BK; ++kk) {
            float4 al = *(const float4*)&As[kk][ty * TM];
            float4 ah = *(const float4*)&As[kk][ty * TM + 4];
            float4 bl = *(const float4*)&Bs[kk][tx * TN];
            float4 bh = *(const float4*)&Bs[kk][tx * TN + 4];
            float af[TM] = {al.x, al.y, al.z, al.w, ah.x, ah.y, ah.z, ah.w};
            float bf[TN] = {bl.x, bl.y, bl.z, bl.w, bh.x, bh.y, bh.z, bh.w};
            #pragma unroll
            for (int i = 0; i < TM; ++i)
                #pragma unroll
                for (int j = 0; j < TN; ++j)
                    acc[i][j] += af[i] * bf[j];
        }
    }

    #pragma unroll
    for (int i = 0; i < TM; ++i) {
        #pragma unroll
        for (int j = 0; j < TN; j += 4) {
            float4 r;
            r.x = acc[i][j + 0];
            r.y = acc[i][j + 1];
            r.z = acc[i][j + 2];
            r.w = acc[i][j + 3];
            *(float4*)&C[(size_t)(row0 + ty * TM + i) * N + col0 + tx * TN + j] = r;
        }
    }
}

// ----------------------------------------------------------------------------
// Kernels
// ----------------------------------------------------------------------------
__global__ void __launch_bounds__(NTHREADS)
qkv_gemm_kernel(const float* __restrict__ x, const float* __restrict__ Wq,
                const float* __restrict__ Wk, const float* __restrict__ Wv)
{
    const float* W;
    float* C;
    if (blockIdx.z == 0)      { W = Wq; C = g_Q; }
    else if (blockIdx.z == 1) { W = Wk; C = g_K; }
    else                      { W = Wv; C = g_V; }
    gemm_nt_tile(x, W, C, 8192, 1024, 1024, 1.0f);
}

__global__ void __launch_bounds__(NTHREADS)
qk_gemm_kernel()
{
    int b = blockIdx.z;
    gemm_nt_tile(g_Q + (size_t)b * 2048 * 1024,
                 g_K + (size_t)b * 2048 * 1024,
                 g_S + (size_t)b * 2048 * 2048,
                 2048, 2048, 1024, 0.03125f);   // 1/sqrt(1024)
}

__global__ void __launch_bounds__(256)
softmax_kernel()
{
    float* p = g_S + (size_t)blockIdx.x * 2048;
    const int t = threadIdx.x;
    __shared__ float red[8];

    float v[8];
    float m = -1e30f;
    #pragma unroll
    for (int i = 0; i < 8; ++i) {
        v[i] = p[t + i * 256];
        m = fmaxf(m, v[i]);
    }
    #pragma unroll
    for (int o = 16; o; o >>= 1) m = fmaxf(m, __shfl_xor_sync(0xffffffffu, m, o));
    if ((t & 31) == 0) red[t >> 5] = m;
    __syncthreads();
    m = red[0];
    #pragma unroll
    for (int i = 1; i < 8; ++i) m = fmaxf(m, red[i]);
    __syncthreads();   // before reusing red[] for the sum

    float s = 0.f;
    #pragma unroll
    for (int i = 0; i < 8; ++i) {
        v[i] = __expf(v[i] - m);
        s += v[i];
    }
    #pragma unroll
    for (int o = 16; o; o >>= 1) s += __shfl_xor_sync(0xffffffffu, s, o);
    if ((t & 31) == 0) red[t >> 5] = s;
    __syncthreads();
    s = red[0];
    #pragma unroll
    for (int i = 1; i < 8; ++i) s += red[i];

    const float inv = 1.0f / s;
    #pragma unroll
    for (int i = 0; i < 8; ++i) p[t + i * 256] = v[i] * inv;
}

__global__ void __launch_bounds__(NTHREADS)
pv_gemm_kernel(float* __restrict__ out)
{
    int b = blockIdx.z;
    gemm_nn_tile(g_S + (size_t)b * 2048 * 2048,
                 g_V + (size_t)b * 2048 * 1024,
                 out + (size_t)b * 2048 * 1024,
                 2048, 1024, 2048);
}

// ----------------------------------------------------------------------------
// Launch
// ----------------------------------------------------------------------------
extern "C" void kernel_launch(void* const* d_in, const int* in_sizes, int n_in,
                              void* d_out, int out_size)
{
    const float* x  = (const float*)d_in[0];
    const float* Wq = (const float*)d_in[1];
    const float* Wk = (const float*)d_in[2];
    const float* Wv = (const float*)d_in[3];
    float* out = (float*)d_out;

    dim3 g1(1024 / BN, 8192 / BM, 3);   // QKV projections
    qkv_gemm_kernel<<<g1, NTHREADS>>>(x, Wq, Wk, Wv);

    dim3 g2(2048 / BN, 2048 / BM, 4);   // scores
    qk_gemm_kernel<<<g2, NTHREADS>>>();

    softmax_kernel<<<4 * 2048, 256>>>();

    dim3 g3(1024 / BN, 2048 / BM, 4);   // P @ V
    pv_gemm_kernel<<<g3, NTHREADS>>>(out);
}

// round 4
// speedup vs baseline: 2.1134x; 2.1134x over previous
#include <cuda_runtime.h>
#include <cuda_bf16.h>
#include <cstdint>

// ============================================================================
// Attention via warp-level mma.sync bf16 split-precision GEMMs (sm_103 generic
// target: no tcgen05 in this toolchain — verified R2).
//   C = Ahi*Bhi + Ahi*Blo + Alo*Bhi   (bf16 m16n8k16 mma, fp32 accum)
// Phases: convert(x,W) -> QKV gemm -> QK gemm -> softmax(split P) -> PV gemm.
// All GEMMs NT (K-contiguous operands); V written transposed so PV is NT too.
// R4 fix: smem stage buffer index is (s+1)&1, NOT s+1 (R3 wrote cp.async far
// past the shared window -> illegal access). Scratch arrays now __align__(256).
// ============================================================================

using bf16 = __nv_bfloat16;

// ---------------- scratch (device globals; no runtime allocation) -----------
__device__ __align__(256) bf16 g_xhi[8192 * 1024], g_xlo[8192 * 1024];
__device__ __align__(256) bf16 g_Whi[3 * 1024 * 1024], g_Wlo[3 * 1024 * 1024];
__device__ __align__(256) bf16 g_Qhi[8192 * 1024], g_Qlo[8192 * 1024];
__device__ __align__(256) bf16 g_Khi[8192 * 1024], g_Klo[8192 * 1024];
__device__ __align__(256) bf16 g_Vthi[4 * 1024 * 2048], g_Vtlo[4 * 1024 * 2048];
__device__ __align__(256) float g_S[4 * 2048 * 2048];
__device__ __align__(256) bf16 g_Phi[4 * 2048 * 2048], g_Plo[4 * 2048 * 2048];

// ---------------- PTX helpers ------------------------------------------------
__device__ __forceinline__ uint32_t smem_u32(const void* p) {
    uint32_t a;
    asm("{ .reg .u64 t; cvta.to.shared.u64 t, %1; cvt.u32.u64 %0, t; }" : "=r"(a) : "l"(p));
    return a;
}
__device__ __forceinline__ void cp16(uint32_t dst, const void* src) {
    asm volatile("cp.async.cg.shared.global [%0], [%1], 16;" :: "r"(dst), "l"(src));
}
#define CP_COMMIT() asm volatile("cp.async.commit_group;" ::: "memory")

__device__ __forceinline__ void ldm4(uint32_t* r, uint32_t a) {
    asm volatile("ldmatrix.sync.aligned.m8n8.x4.shared.b16 {%0,%1,%2,%3}, [%4];"
                 : "=r"(r[0]), "=r"(r[1]), "=r"(r[2]), "=r"(r[3]) : "r"(a));
}
__device__ __forceinline__ void mma_bf16(float* c, const uint32_t* a, uint32_t b0, uint32_t b1) {
    asm volatile(
        "mma.sync.aligned.m16n8k16.row.col.f32.bf16.bf16.f32 "
        "{%0,%1,%2,%3}, {%4,%5,%6,%7}, {%8,%9}, {%0,%1,%2,%3};"
        : "+f"(c[0]), "+f"(c[1]), "+f"(c[2]), "+f"(c[3])
        : "r"(a[0]), "r"(a[1]), "r"(a[2]), "r"(a[3]), "r"(b0), "r"(b1));
}

__device__ __forceinline__ void split_store(float v, bf16* hi, bf16* lo, size_t o) {
    bf16 h = __float2bfloat16(v);
    hi[o] = h;
    lo[o] = __float2bfloat16(v - __bfloat162float(h));
}

// ---------------- SMEM layout -------------------------------------------------
// Per stage: Ahi, Alo, Bhi, Blo — each 128 rows x 32 bf16, padded row stride
// 40 bf16 (80B) => conflict-free ldmatrix (r*20 words mod 32 all distinct).
#define ROWB     80
#define ARR_B    (128 * ROWB)     // 10240
#define STG_B    (4 * ARR_B)      // 40960
#define SM_TOTAL (2 * STG_B)      // 81920

// ---------------- GEMM body ---------------------------------------------------
// MODE 0: QKV (z: 0->Q, 1->K, 2->V-transposed), split-bf16 outputs
// MODE 1: QK  (z=batch), S = acc/32 fp32
// MODE 2: PV  (z=batch), out = acc fp32
template <int MODE>
__device__ __forceinline__ void gemm_body(
    const bf16* __restrict__ Ah, const bf16* __restrict__ Al, int lda,
    const bf16* __restrict__ Bh, const bf16* __restrict__ Bl, int ldb,
    int K, float* __restrict__ outp)
{
    extern __shared__ char sm[];
    const uint32_t smb = smem_u32(sm);
    const int tid = threadIdx.x, lane = tid & 31, wid = tid >> 5;
    const int wm = wid & 1, wn = wid >> 1;          // warp tile: 64x32
    const int row0 = blockIdx.y * 128, col0 = blockIdx.x * 128;

    float acc[4][4][4];
    #pragma unroll
    for (int i = 0; i < 4; ++i)
        #pragma unroll
        for (int j = 0; j < 4; ++j)
            #pragma unroll
            for (int k = 0; k < 4; ++k) acc[i][j][k] = 0.f;

    // ---- global->smem loader (cp.async), 8 x 16B per thread per stage ----
    const int lr = tid >> 2;              // 0..63
    const int lk = (tid & 3) * 8;         // element offset in K
    const uint32_t soff = lr * ROWB + lk * 2;
    const bf16* pa  = Ah + (size_t)(row0 + lr) * lda + lk;
    const bf16* pal = Al + (size_t)(row0 + lr) * lda + lk;
    const bf16* pb  = Bh + (size_t)(col0 + lr) * ldb + lk;
    const bf16* pbl = Bl + (size_t)(col0 + lr) * ldb + lk;

    auto load_stage = [&](int sbuf, int k0) {
        uint32_t b = smb + sbuf * STG_B + soff;
        cp16(b,                         pa  + k0);
        cp16(b + 64 * ROWB,             pa  + k0 + (size_t)64 * lda);
        cp16(b + ARR_B,                 pal + k0);
        cp16(b + ARR_B + 64 * ROWB,     pal + k0 + (size_t)64 * lda);
        cp16(b + 2 * ARR_B,             pb  + k0);
        cp16(b + 2 * ARR_B + 64 * ROWB, pb  + k0 + (size_t)64 * ldb);
        cp16(b + 3 * ARR_B,             pbl + k0);
        cp16(b + 3 * ARR_B + 64 * ROWB, pbl + k0 + (size_t)64 * ldb);
        CP_COMMIT();
    };

    const int ns = K >> 5;   // 32 K per stage
    load_stage(0, 0);

    // ldmatrix base offsets (bytes within stage)
    const uint32_t a_off = (wm * 64 + (lane & 15)) * ROWB + (lane >> 4) * 16;
    const uint32_t b_off = (wn * 32 + (lane & 7) + ((lane >> 4) << 3)) * ROWB
                         + ((lane >> 3) & 1) * 16;

    for (int s = 0; s < ns; ++s) {
        if (s + 1 < ns) {
            load_stage((s + 1) & 1, (s + 1) * 32);   // R4 FIX: buffer = (s+1)&1
            asm volatile("cp.async.wait_group 1;" ::: "memory");
        } else {
            asm volatile("cp.async.wait_group 0;" ::: "memory");
        }
        __syncthreads();

        const uint32_t sb = smb + (s & 1) * STG_B;
        #pragma unroll
        for (int ks = 0; ks < 2; ++ks) {
            const uint32_t ab = sb + a_off + ks * 32;
            const uint32_t bb = sb + 2 * ARR_B + b_off + ks * 32;
            uint32_t ah[4][4], al[4][4], bh[2][4], bl[2][4];
            #pragma unroll
            for (int mt = 0; mt < 4; ++mt) {
                ldm4(ah[mt], ab + mt * 16 * ROWB);
                ldm4(al[mt], ab + ARR_B + mt * 16 * ROWB);
            }
            #pragma unroll
            for (int bt = 0; bt < 2; ++bt) {
                ldm4(bh[bt], bb + bt * 16 * ROWB);
                ldm4(bl[bt], bb + ARR_B + bt * 16 * ROWB);
            }
            #pragma unroll
            for (int mt = 0; mt < 4; ++mt)
                #pragma unroll
                for (int nt = 0; nt < 4; ++nt) {
                    const int bt = nt >> 1, h = (nt & 1) * 2;
                    mma_bf16(acc[mt][nt], ah[mt], bh[bt][h], bh[bt][h + 1]);
                    mma_bf16(acc[mt][nt], ah[mt], bl[bt][h], bl[bt][h + 1]);
                    mma_bf16(acc[mt][nt], al[mt], bh[bt][h], bh[bt][h + 1]);
                }
        }
        __syncthreads();
    }

    // ---- epilogue: register fragments -> global ----
    const int z = blockIdx.z;
    const int gr0 = row0 + wm * 64 + (lane >> 2);
    const int gc0 = col0 + wn * 32 + (lane & 3) * 2;

    #pragma unroll
    for (int mt = 0; mt < 4; ++mt) {
        #pragma unroll
        for (int nt = 0; nt < 4; ++nt) {
            const int gr = gr0 + mt * 16;
            const int gc = gc0 + nt * 8;
            const float* c = acc[mt][nt];
            if (MODE == 0) {
                if (z == 2) {
                    // V transposed: Vt[(b*1024 + n)][t]
                    const int b = gr >> 11, t = gr & 2047;
                    const size_t o = ((size_t)(b * 1024 + gc)) * 2048 + t;
                    split_store(c[0], g_Vthi, g_Vtlo, o);
                    split_store(c[1], g_Vthi, g_Vtlo, o + 2048);
                    split_store(c[2], g_Vthi, g_Vtlo, o + 8);
                    split_store(c[3], g_Vthi, g_Vtlo, o + 2048 + 8);
                } else {
                    bf16* hi = (z == 0) ? g_Qhi : g_Khi;
                    bf16* lo = (z == 0) ? g_Qlo : g_Klo;
                    const size_t o = (size_t)gr * 1024 + gc;
                    split_store(c[0], hi, lo, o);
                    split_store(c[1], hi, lo, o + 1);
                    split_store(c[2], hi, lo, o + 8 * 1024);
                    split_store(c[3], hi, lo, o + 8 * 1024 + 1);
                }
            } else if (MODE == 1) {
                float* p = g_S + ((size_t)z << 22) + (size_t)gr * 2048 + gc;
                *(float2*)p            = make_float2(c[0] * 0.03125f, c[1] * 0.03125f);
                *(float2*)(p + 8*2048) = make_float2(c[2] * 0.03125f, c[3] * 0.03125f);
            } else {
                float* p = outp + ((size_t)z << 21) + (size_t)gr * 1024 + gc;
                *(float2*)p            = make_float2(c[0], c[1]);
                *(float2*)(p + 8*1024) = make_float2(c[2], c[3]);
            }
        }
    }
}

// ---------------- kernels -----------------------------------------------------
__global__ void __launch_bounds__(256)
qkv_kernel()
{
    int z = blockIdx.z;
    gemm_body<0>(g_xhi, g_xlo, 1024,
                 g_Whi + (size_t)z * 1024 * 1024, g_Wlo + (size_t)z * 1024 * 1024, 1024,
                 1024, nullptr);
}

__global__ void __launch_bounds__(256)
qk_kernel()
{
    size_t bo = (size_t)blockIdx.z << 21;   // b*2048*1024
    gemm_body<1>(g_Qhi + bo, g_Qlo + bo, 1024,
                 g_Khi + bo, g_Klo + bo, 1024,
                 1024, nullptr);
}

__global__ void __launch_bounds__(256)
pv_kernel(float* __restrict__ out)
{
    size_t ao = (size_t)blockIdx.z << 22;   // b*2048*2048
    size_t bo = (size_t)blockIdx.z << 21;   // b*1024*2048
    gemm_body<2>(g_Phi + ao, g_Plo + ao, 2048,
                 g_Vthi + bo, g_Vtlo + bo, 2048,
                 2048, out);
}

__global__ void __launch_bounds__(256)
convert_kernel(const float* __restrict__ src, bf16* __restrict__ hi,
               bf16* __restrict__ lo, int n4)
{
    int i = blockIdx.x * blockDim.x + threadIdx.x;
    if (i < n4) {
        float4 v = *(const float4*)(src + i * 4);
        float f[4] = {v.x, v.y, v.z, v.w};
        #pragma unroll
        for (int j = 0; j < 4; ++j) {
            bf16 h = __float2bfloat16(f[j]);
            hi[i * 4 + j] = h;
            lo[i * 4 + j] = __float2bfloat16(f[j] - __bfloat162float(h));
        }
    }
}

__global__ void __launch_bounds__(256)
softmax_kernel()
{
    size_t ro = (size_t)blockIdx.x * 2048;
    const float* p = g_S + ro;
    const int t = threadIdx.x;
    __shared__ float red[8];

    float v[8];
    float m = -1e30f;
    #pragma unroll
    for (int i = 0; i < 8; ++i) {
        v[i] = p[t + i * 256];
        m = fmaxf(m, v[i]);
    }
    #pragma unroll
    for (int o = 16; o; o >>= 1) m = fmaxf(m, __shfl_xor_sync(0xffffffffu, m, o));
    if ((t & 31) == 0) red[t >> 5] = m;
    __syncthreads();
    m = red[0];
    #pragma unroll
    for (int i = 1; i < 8; ++i) m = fmaxf(m, red[i]);
    __syncthreads();

    float s = 0.f;
    #pragma unroll
    for (int i = 0; i < 8; ++i) {
        v[i] = __expf(v[i] - m);
        s += v[i];
    }
    #pragma unroll
    for (int o = 16; o; o >>= 1) s += __shfl_xor_sync(0xffffffffu, s, o);
    if ((t & 31) == 0) red[t >> 5] = s;
    __syncthreads();
    s = red[0];
    #pragma unroll
    for (int i = 1; i < 8; ++i) s += red[i];

    const float inv = 1.0f / s;
    #pragma unroll
    for (int i = 0; i < 8; ++i) {
        float pv = v[i] * inv;
        size_t o = ro + t + i * 256;
        bf16 h = __float2bfloat16(pv);
        g_Phi[o] = h;
        g_Plo[o] = __float2bfloat16(pv - __bfloat162float(h));
    }
}

// ---------------- launch ------------------------------------------------------
extern "C" void kernel_launch(void* const* d_in, const int* in_sizes, int n_in,
                              void* d_out, int out_size)
{
    const float* x  = (const float*)d_in[0];
    const float* Wq = (const float*)d_in[1];
    const float* Wk = (const float*)d_in[2];
    const float* Wv = (const float*)d_in[3];
    float* out = (float*)d_out;

    cudaFuncSetAttribute(qkv_kernel, cudaFuncAttributeMaxDynamicSharedMemorySize, SM_TOTAL);
    cudaFuncSetAttribute(qk_kernel,  cudaFuncAttributeMaxDynamicSharedMemorySize, SM_TOTAL);
    cudaFuncSetAttribute(pv_kernel,  cudaFuncAttributeMaxDynamicSharedMemorySize, SM_TOTAL);

    bf16 *xhi, *xlo, *whi, *wlo;
    cudaGetSymbolAddress((void**)&xhi, g_xhi);
    cudaGetSymbolAddress((void**)&xlo, g_xlo);
    cudaGetSymbolAddress((void**)&whi, g_Whi);
    cudaGetSymbolAddress((void**)&wlo, g_Wlo);

    {
        int n4 = 8192 * 1024 / 4;
        convert_kernel<<<(n4 + 255) / 256, 256>>>(x, xhi, xlo, n4);
    }
    {
        int n4 = 1024 * 1024 / 4;
        convert_kernel<<<(n4 + 255) / 256, 256>>>(Wq, whi, wlo, n4);
        convert_kernel<<<(n4 + 255) / 256, 256>>>(Wk, whi + 1024 * 1024, wlo + 1024 * 1024, n4);
        convert_kernel<<<(n4 + 255) / 256, 256>>>(Wv, whi + 2 * 1024 * 1024, wlo + 2 * 1024 * 1024, n4);
    }

    dim3 g1(8, 64, 3);    // QKV: N=1024/128, M=8192/128
    qkv_kernel<<<g1, 256, SM_TOTAL>>>();

    dim3 g2(16, 16, 4);   // QK: 2048x2048 per batch
    qk_kernel<<<g2, 256, SM_TOTAL>>>();

    softmax_kernel<<<4 * 2048, 256>>>();

    dim3 g3(8, 16, 4);    // PV: 2048x1024, K=2048
    pv_kernel<<<g3, 256, SM_TOTAL>>>(out);
}